// round 2
// baseline (speedup 1.0000x reference)
#include <cuda_runtime.h>
#include <cuda_bf16.h>

#define N_NODES 100000
#define C 32
#define E_EDGES 3200000
#define SPMM_WARPS 8

// ---- scratch (no allocations allowed) ----
__device__ float  g_deg[N_NODES];
__device__ float2 g_node[N_NODES];        // .x = dinv, .y = int_as_float(label if masked else -1)
__device__ float  g_q[N_NODES * C];       // q[c][j] = dinv[c] * p[c][j]
__device__ float  g_H[C * C];             // unnormalized class-compat accumulator
__device__ int    g_mode;                 // mask dtype: 0=u8, 1=i32, 2=f32, 3=bf16

// ---------------------------------------------------------------- mask dtype sniffing
__global__ void k_detect(const unsigned char* __restrict__ m) {
    if (threadIdx.x == 0) {
        int nz[4] = {0, 0, 0, 0};
        int c01 = 0, c3F = 0;
        for (int i = 0; i < 4096; i++) {
            unsigned char b = m[i];
            if (b) {
                nz[i & 3]++;
                if (b == 0x01) c01++;
                if (b == 0x3F) c3F++;
            }
        }
        int mode;
        if (nz[1] == 0 && nz[2] == 0 && nz[3] == 0)
            mode = 1;                                        // int32 (0/1, LE: nonzero only at %4==0)
        else if (c01 == 0 && c3F > 0)
            mode = (nz[0] == 0 && nz[1] == 0) ? 2 : 3;       // float32 (00 00 80 3F) : bf16 (80 3F)
        else
            mode = 0;                                        // uint8 bool
        g_mode = mode;
    }
}

__device__ __forceinline__ bool read_mask(const unsigned char* p, int node, int mode) {
    if (mode == 1) return ((const int*)p)[node] != 0;
    if (mode == 2) return ((const float*)p)[node] != 0.0f;
    if (mode == 3) return ((const unsigned short*)p)[node] != 0;
    return p[node] != 0;
}

// ---------------------------------------------------------------- init
__global__ void k_init() {
    int i = blockIdx.x * blockDim.x + threadIdx.x;
    if (i < N_NODES) g_deg[i] = 1.0f;          // self-loop weight
    if (i < C * C)   g_H[i]   = 0.0f;
}

// ---------------------------------------------------------------- degree
__global__ void k_deg(const int* __restrict__ row, const float* __restrict__ w) {
    int i = blockIdx.x * blockDim.x + threadIdx.x;
    int stride = gridDim.x * blockDim.x;
    for (int e = i; e < E_EDGES; e += stride)
        atomicAdd(&g_deg[row[e]], w[e]);
}

// ---------------------------------------------------------------- per-node: softmax / mask / dinv / q / self-loop diag
__global__ __launch_bounds__(256) void k_node(const float* __restrict__ x,
                                              const float* __restrict__ y,
                                              const unsigned char* __restrict__ mask) {
    __shared__ float sdiag[C];
    int tid  = threadIdx.x;
    int lane = tid & 31;
    int wid  = tid >> 5;
    if (tid < C) sdiag[tid] = 0.0f;
    __syncthreads();

    int mode = g_mode;
    int node = blockIdx.x * 8 + wid;   // one warp per node
    if (node < N_NODES) {
        float xi = x[node * C + lane];
        float mx = xi;
        #pragma unroll
        for (int o = 16; o; o >>= 1) mx = fmaxf(mx, __shfl_xor_sync(0xFFFFFFFFu, mx, o));
        float ex = __expf(xi - mx);
        float s = ex;
        #pragma unroll
        for (int o = 16; o; o >>= 1) s += __shfl_xor_sync(0xFFFFFFFFu, s, o);
        float p = ex / s;

        float yv = y[node * C + lane];
        unsigned b = __ballot_sync(0xFFFFFFFFu, yv > 0.5f);
        int label = __ffs(b) - 1;

        bool m = read_mask(mask, node, mode);
        if (m) p = yv;                       // masked nodes broadcast their label

        float dinv = rsqrtf(g_deg[node]);    // deg >= 1 always
        g_q[node * C + lane] = dinv * p;

        if (lane == 0) {
            int li = m ? label : -1;
            g_node[node] = make_float2(dinv, __int_as_float(li));
            if (m) atomicAdd(&sdiag[label], dinv * dinv);   // self-loop: p[r]=e_label
        }
    }
    __syncthreads();
    if (tid < C) {
        float v = sdiag[tid];
        if (v != 0.0f) atomicAdd(&g_H[tid * C + tid], v);
    }
}

// ---------------------------------------------------------------- fused edge sweep -> 32x32 tile
// Warp-private SMEM tile; lane j is the SOLE writer of column j -> no atomics in hot loop.
__global__ __launch_bounds__(256) void k_spmm(const int* __restrict__ row,
                                              const int* __restrict__ col,
                                              const float* __restrict__ w) {
    __shared__ float Hs[SPMM_WARPS][C * C];
    int lane = threadIdx.x & 31;
    int wid  = threadIdx.x >> 5;
    float* Hw = Hs[wid];
    for (int i = lane; i < C * C; i += 32) Hw[i] = 0.0f;
    __syncwarp();

    int warpGlobal = blockIdx.x * SPMM_WARPS + wid;
    int nwarps = gridDim.x * SPMM_WARPS;

    for (int base = warpGlobal * 32; base < E_EDGES; base += nwarps * 32) {
        int e = base + lane;
        bool inb = (e < E_EDGES);
        int   r  = inb ? row[e] : 0;
        int   c  = inb ? col[e] : 0;
        float we = inb ? w[e]   : 0.0f;
        float2 nf = inb ? g_node[r] : make_float2(0.0f, __int_as_float(-1));
        int   lr = __float_as_int(nf.y);
        float vw = nf.x * we;

        unsigned keep = __ballot_sync(0xFFFFFFFFu, inb && lr >= 0);
        while (keep) {
            // extract up to 4 edges -> MLP=4 on the q gathers
            int k0 = __ffs(keep) - 1; keep &= keep - 1;
            bool h1 = keep != 0; int k1 = k0;
            if (h1) { k1 = __ffs(keep) - 1; keep &= keep - 1; }
            bool h2 = keep != 0; int k2 = k0;
            if (h2) { k2 = __ffs(keep) - 1; keep &= keep - 1; }
            bool h3 = keep != 0; int k3 = k0;
            if (h3) { k3 = __ffs(keep) - 1; keep &= keep - 1; }

            int   c0 = __shfl_sync(0xFFFFFFFFu, c,  k0);
            float v0 = __shfl_sync(0xFFFFFFFFu, vw, k0);
            int   l0 = __shfl_sync(0xFFFFFFFFu, lr, k0);
            int   c1 = __shfl_sync(0xFFFFFFFFu, c,  k1);
            float v1 = __shfl_sync(0xFFFFFFFFu, vw, k1);
            int   l1 = __shfl_sync(0xFFFFFFFFu, lr, k1);
            int   c2 = __shfl_sync(0xFFFFFFFFu, c,  k2);
            float v2 = __shfl_sync(0xFFFFFFFFu, vw, k2);
            int   l2 = __shfl_sync(0xFFFFFFFFu, lr, k2);
            int   c3 = __shfl_sync(0xFFFFFFFFu, c,  k3);
            float v3 = __shfl_sync(0xFFFFFFFFu, vw, k3);
            int   l3 = __shfl_sync(0xFFFFFFFFu, lr, k3);

            float p0 =      g_q[c0 * C + lane];
            float p1 = h1 ? g_q[c1 * C + lane] : 0.0f;
            float p2 = h2 ? g_q[c2 * C + lane] : 0.0f;
            float p3 = h3 ? g_q[c3 * C + lane] : 0.0f;

            Hw[l0 * C + lane] += v0 * p0;
            if (h1) Hw[l1 * C + lane] += v1 * p1;
            if (h2) Hw[l2 * C + lane] += v2 * p2;
            if (h3) Hw[l3 * C + lane] += v3 * p3;
        }
    }

    __syncthreads();
    for (int i = threadIdx.x; i < C * C; i += blockDim.x) {
        float s = 0.0f;
        #pragma unroll
        for (int wg = 0; wg < SPMM_WARPS; wg++) s += Hs[wg][i];
        atomicAdd(&g_H[i], s);
    }
}

// ---------------------------------------------------------------- Sinkhorn (1 warp, register columns, smem transpose ping-pong)
__global__ void k_sinkhorn(float* __restrict__ out) {
    __shared__ float ss[C * 33];
    int t = threadIdx.x;   // thread t holds column t

    float v[C];
    #pragma unroll
    for (int r = 0; r < C; r++) v[r] = g_H[r * C + t];

    for (int it = 0; it < 3000; it++) {
        // column normalize (local)
        float s = 0.0f;
        #pragma unroll
        for (int r = 0; r < C; r++) s += v[r];
        float inv = 1.0f / s;
        #pragma unroll
        for (int r = 0; r < C; r++) { v[r] *= inv; ss[r * 33 + t] = v[r]; }
        __syncwarp();

        // read row t (transpose), row normalize (local)
        float u[C];
        float s2 = 0.0f;
        #pragma unroll
        for (int cc = 0; cc < C; cc++) { u[cc] = ss[t * 33 + cc]; s2 += u[cc]; }
        float inv2 = 1.0f / s2;
        __syncwarp();
        #pragma unroll
        for (int cc = 0; cc < C; cc++) { u[cc] *= inv2; ss[t * 33 + cc] = u[cc]; }
        __syncwarp();
        #pragma unroll
        for (int r = 0; r < C; r++) v[r] = ss[r * 33 + t];
        __syncwarp();

        // at the fixed point both scale factors -> 1; early exit (result identical
        // to the reference's fixed 3000 iterations within fp32)
        float dev = fmaxf(fabsf(s - 1.0f), fabsf(s2 - 1.0f));
        if (it >= 5 && __all_sync(0xFFFFFFFFu, dev < 1e-5f)) break;
    }

    #pragma unroll
    for (int r = 0; r < C; r++) out[r * C + t] = v[r];
}

// ---------------------------------------------------------------- launch
extern "C" void kernel_launch(void* const* d_in, const int* in_sizes, int n_in,
                              void* d_out, int out_size) {
    const int*           ei   = (const int*)d_in[0];      // (2, E): rows then cols
    const float*         ew   = (const float*)d_in[1];    // (E,)
    const float*         x    = (const float*)d_in[2];    // (N, C)
    const float*         y    = (const float*)d_in[3];    // (N, C) one-hot
    const unsigned char* mask = (const unsigned char*)d_in[4];  // (N,) bool-ish (dtype sniffed)

    const int* row = ei;
    const int* col = ei + E_EDGES;

    k_detect<<<1, 32>>>(mask);
    k_init<<<(N_NODES + 255) / 256, 256>>>();
    k_deg<<<592, 256>>>(row, ew);
    k_node<<<(N_NODES + 7) / 8, 256>>>(x, y, mask);
    k_spmm<<<1036, 256>>>(row, col, ew);
    k_sinkhorn<<<1, 32>>>((float*)d_out);
}

// round 7
// speedup vs baseline: 1.0891x; 1.0891x over previous
#include <cuda_runtime.h>
#include <cuda_bf16.h>

#define N_NODES 100000
#define C 32
#define E_EDGES 3200000
#define SPMM_WARPS 8

// ---- scratch (no allocations allowed) ----
__device__ float         g_deg[N_NODES];
__device__ float2        g_node[N_NODES];       // .x = dinv, .y = int_as_float(label if masked else -1)
__device__ __nv_bfloat16 g_qh[N_NODES * C];     // q[c][j] = dinv[c] * p[c][j], bf16
__device__ int2          g_cmp[E_EDGES];        // compacted kept edges: {col | label<<17, f32 vw}
__device__ float         g_H[C * C];            // unnormalized class-compat accumulator
__device__ int           g_mode;                // mask dtype: 0=u8, 1=i32, 2=f32, 3=bf16
__device__ int           g_cnt;                 // kept-edge count

// ---------------------------------------------------------------- mask dtype sniffing (warp-parallel)
__global__ void k_detect(const unsigned char* __restrict__ m) {
    int lane = threadIdx.x;
    int nz0 = 0, nz1 = 0, nz2 = 0, nz3 = 0, c01 = 0, c3F = 0;
    for (int base = 0; base < 4096; base += 32) {
        unsigned char b = m[base + lane];        // (base+lane)&3 == lane&3
        unsigned nzm = __ballot_sync(0xFFFFFFFFu, b != 0);
        unsigned m01 = __ballot_sync(0xFFFFFFFFu, b == 0x01);
        unsigned m3F = __ballot_sync(0xFFFFFFFFu, b == 0x3F);
        nz0 += __popc(nzm & 0x11111111u);
        nz1 += __popc(nzm & 0x22222222u);
        nz2 += __popc(nzm & 0x44444444u);
        nz3 += __popc(nzm & 0x88888888u);
        c01 += __popc(m01);
        c3F += __popc(m3F);
    }
    if (lane == 0) {
        int mode;
        if (nz1 == 0 && nz2 == 0 && nz3 == 0)
            mode = 1;                                        // int32 (0/1, LE)
        else if (c01 == 0 && c3F > 0)
            mode = (nz0 == 0 && nz1 == 0) ? 2 : 3;           // float32 : bf16
        else
            mode = 0;                                        // uint8 bool
        g_mode = mode;
    }
}

__device__ __forceinline__ bool read_mask(const unsigned char* p, int node, int mode) {
    if (mode == 1) return ((const int*)p)[node] != 0;
    if (mode == 2) return ((const float*)p)[node] != 0.0f;
    if (mode == 3) return ((const unsigned short*)p)[node] != 0;
    return p[node] != 0;
}

// ---------------------------------------------------------------- init
__global__ void k_init() {
    int i = blockIdx.x * blockDim.x + threadIdx.x;
    if (i < N_NODES) g_deg[i] = 1.0f;          // self-loop weight
    if (i < C * C)   g_H[i]   = 0.0f;
    if (i == 0)      g_cnt    = 0;
}

// ---------------------------------------------------------------- degree (vectorized)
__global__ void k_deg(const int4* __restrict__ row4, const float4* __restrict__ w4) {
    int e = blockIdx.x * blockDim.x + threadIdx.x;
    if (e < E_EDGES / 4) {
        int4   r = row4[e];
        float4 w = w4[e];
        atomicAdd(&g_deg[r.x], w.x);
        atomicAdd(&g_deg[r.y], w.y);
        atomicAdd(&g_deg[r.z], w.z);
        atomicAdd(&g_deg[r.w], w.w);
    }
}

// ---------------------------------------------------------------- per-node: softmax / mask / dinv / q / self-loop diag
// Thread-per-node via smem transpose: zero cross-lane ops in the hot path.
__global__ __launch_bounds__(256) void k_node(const float* __restrict__ x,
                                              const float* __restrict__ y,
                                              const unsigned char* __restrict__ mask) {
    __shared__ float tile[256 * 33];
    __shared__ int   slab[256];
    __shared__ float sdiag[C];
    int tid   = threadIdx.x;
    int node0 = blockIdx.x * 256;
    int base  = node0 * C;
    int lim   = min(256 * C, (N_NODES - node0) * C);
    if (tid < C) sdiag[tid] = 0.0f;

    // labels: exploit one-hot — record column of the single >0.5 entry
    for (int i = tid; i < lim; i += 256)
        if (y[base + i] > 0.5f) slab[i >> 5] = i & 31;
    // coalesced x tile load (padded stride 33 -> conflict-free row reads)
    for (int i = tid; i < lim; i += 256)
        tile[(i >> 5) * 33 + (i & 31)] = x[base + i];
    __syncthreads();

    int node = node0 + tid;
    if (node < N_NODES) {
        bool  msk  = read_mask(mask, node, g_mode);
        float dinv = rsqrtf(g_deg[node]);       // deg >= 1 always
        float* row = &tile[tid * 33];
        if (msk) {
            int l = slab[tid];
            #pragma unroll
            for (int c = 0; c < C; c++) row[c] = 0.0f;
            row[l] = dinv;                      // q = dinv * onehot(label)
            atomicAdd(&sdiag[l], dinv * dinv);  // self-loop diag contribution
            g_node[node] = make_float2(dinv, __int_as_float(l));
        } else {
            float v[C];
            float mx = -1e30f;
            #pragma unroll
            for (int c = 0; c < C; c++) { v[c] = row[c]; mx = fmaxf(mx, v[c]); }
            float s = 0.0f;
            #pragma unroll
            for (int c = 0; c < C; c++) { v[c] = __expf(v[c] - mx); s += v[c]; }
            float f = dinv / s;
            #pragma unroll
            for (int c = 0; c < C; c++) row[c] = v[c] * f;
            g_node[node] = make_float2(dinv, __int_as_float(-1));
        }
    }
    __syncthreads();

    // coalesced bf16 store of q
    for (int i = tid; i < lim; i += 256)
        g_qh[base + i] = __float2bfloat16(tile[(i >> 5) * 33 + (i & 31)]);
    if (tid < C && sdiag[tid] != 0.0f) atomicAdd(&g_H[tid * C + tid], sdiag[tid]);
}

// ---------------------------------------------------------------- compaction: keep masked-row edges, pack {col|label<<17, vw}
__global__ __launch_bounds__(256) void k_compact(const int* __restrict__ row,
                                                 const int* __restrict__ col,
                                                 const float* __restrict__ w) {
    int lane = threadIdx.x & 31;
    int gw   = (blockIdx.x * blockDim.x + threadIdx.x) >> 5;
    int nw   = (gridDim.x * blockDim.x) >> 5;
    for (int be = gw * 32; be < E_EDGES; be += nw * 32) {   // E % 32 == 0
        int   e  = be + lane;
        int   r  = row[e];
        int   c  = col[e];
        float we = w[e];
        float2 nf = g_node[r];
        int   lr = __float_as_int(nf.y);
        bool  keep = (lr >= 0);
        unsigned bal = __ballot_sync(0xFFFFFFFFu, keep);
        int n = __popc(bal);
        int pos = 0;
        if (lane == 0 && n) pos = atomicAdd(&g_cnt, n);
        pos = __shfl_sync(0xFFFFFFFFu, pos, 0);
        if (keep) {
            int off = __popc(bal & ((1u << lane) - 1u));
            g_cmp[pos + off] = make_int2(c | (lr << 17), __float_as_int(nf.x * we));
        }
    }
}

// ---------------------------------------------------------------- dense sweep -> 32x32 tile
// Broadcast model: one edge per inner step; lane j sole owner of column j -> no atomics.
__global__ __launch_bounds__(256) void k_spmm() {
    __shared__ float Hs[SPMM_WARPS][C * C];
    int lane = threadIdx.x & 31;
    int wid  = threadIdx.x >> 5;
    float* Hw = Hs[wid];
    for (int i = lane; i < C * C; i += 32) Hw[i] = 0.0f;
    __syncwarp();

    int total = g_cnt;
    int gw = blockIdx.x * SPMM_WARPS + wid;
    int nw = gridDim.x * SPMM_WARPS;

    for (int base = gw * 32; base < total; base += nw * 32) {
        int e = base + lane;
        int2 ent = (e < total) ? g_cmp[e] : make_int2(0, 0);
        if (base + 32 <= total) {
            #pragma unroll
            for (int k = 0; k < 32; k++) {
                int   pk = __shfl_sync(0xFFFFFFFFu, ent.x, k);
                float v  = __uint_as_float(__shfl_sync(0xFFFFFFFFu, ent.y, k));
                int c = pk & 0x1FFFF;
                int l = pk >> 17;
                float qv = __bfloat162float(g_qh[c * C + lane]);
                Hw[l * C + lane] += v * qv;
            }
        } else {
            int cnt = total - base;
            for (int k = 0; k < cnt; k++) {
                int   pk = __shfl_sync(0xFFFFFFFFu, ent.x, k);
                float v  = __uint_as_float(__shfl_sync(0xFFFFFFFFu, ent.y, k));
                int c = pk & 0x1FFFF;
                int l = pk >> 17;
                float qv = __bfloat162float(g_qh[c * C + lane]);
                Hw[l * C + lane] += v * qv;
            }
        }
    }

    __syncthreads();
    for (int i = threadIdx.x; i < C * C; i += blockDim.x) {
        float s = 0.0f;
        #pragma unroll
        for (int wg = 0; wg < SPMM_WARPS; wg++) s += Hs[wg][i];
        atomicAdd(&g_H[i], s);
    }
}

// ---------------------------------------------------------------- Sinkhorn (unchanged — verified correct)
__global__ void k_sinkhorn(float* __restrict__ out) {
    __shared__ float ss[C * 33];
    int t = threadIdx.x;   // thread t holds column t

    float v[C];
    #pragma unroll
    for (int r = 0; r < C; r++) v[r] = g_H[r * C + t];

    for (int it = 0; it < 3000; it++) {
        float s = 0.0f;
        #pragma unroll
        for (int r = 0; r < C; r++) s += v[r];
        float inv = 1.0f / s;
        #pragma unroll
        for (int r = 0; r < C; r++) { v[r] *= inv; ss[r * 33 + t] = v[r]; }
        __syncwarp();

        float u[C];
        float s2 = 0.0f;
        #pragma unroll
        for (int cc = 0; cc < C; cc++) { u[cc] = ss[t * 33 + cc]; s2 += u[cc]; }
        float inv2 = 1.0f / s2;
        __syncwarp();
        #pragma unroll
        for (int cc = 0; cc < C; cc++) { u[cc] *= inv2; ss[t * 33 + cc] = u[cc]; }
        __syncwarp();
        #pragma unroll
        for (int r = 0; r < C; r++) v[r] = ss[r * 33 + t];
        __syncwarp();

        float dev = fmaxf(fabsf(s - 1.0f), fabsf(s2 - 1.0f));
        if (it >= 5 && __all_sync(0xFFFFFFFFu, dev < 1e-5f)) break;
    }

    #pragma unroll
    for (int r = 0; r < C; r++) out[r * C + t] = v[r];
}

// ---------------------------------------------------------------- launch
extern "C" void kernel_launch(void* const* d_in, const int* in_sizes, int n_in,
                              void* d_out, int out_size) {
    const int*           ei   = (const int*)d_in[0];      // (2, E): rows then cols
    const float*         ew   = (const float*)d_in[1];    // (E,)
    const float*         x    = (const float*)d_in[2];    // (N, C)
    const float*         y    = (const float*)d_in[3];    // (N, C) one-hot
    const unsigned char* mask = (const unsigned char*)d_in[4];  // (N,) dtype sniffed

    const int* row = ei;
    const int* col = ei + E_EDGES;

    k_detect<<<1, 32>>>(mask);
    k_init<<<(N_NODES + 255) / 256, 256>>>();
    k_deg<<<(E_EDGES / 4 + 255) / 256, 256>>>((const int4*)row, (const float4*)ew);
    k_node<<<(N_NODES + 255) / 256, 256>>>(x, y, mask);
    k_compact<<<1184, 256>>>(row, col, ew);
    k_spmm<<<592, 256>>>();
    k_sinkhorn<<<1, 32>>>((float*)d_out);
}

// round 8
// speedup vs baseline: 1.6988x; 1.5598x over previous
#include <cuda_runtime.h>
#include <cuda_bf16.h>
#include <string.h>

#define N_NODES 100000
#define C 32
#define E_EDGES 3200000
#define SPMM_WARPS 8

// ---- scratch (no allocations allowed) ----
__device__ float         g_deg[N_NODES];
__device__ float         g_ld[N_NODES];         // fp32 dinv, low 6 mantissa bits = (32|label) if masked else 0
__device__ __nv_bfloat16 g_qh[N_NODES * C];     // q[c][j] = dinv[c] * p[c][j], bf16
__device__ int2          g_cmp[E_EDGES];        // compacted kept edges: {col | label<<17, f32 vw}
__device__ float         g_H[C * C];            // unnormalized class-compat accumulator
__device__ int           g_mode;                // mask dtype: 0=u8, 1=i32, 2=f32, 3=bf16
__device__ int           g_cnt;                 // kept-edge count

// ---------------------------------------------------------------- init + mask dtype sniffing (block 0, warp 0)
__global__ void k_init(const unsigned char* __restrict__ m) {
    int i = blockIdx.x * blockDim.x + threadIdx.x;
    if (i < N_NODES) g_deg[i] = 1.0f;          // self-loop weight
    if (i < C * C)   g_H[i]   = 0.0f;
    if (i == 0)      g_cnt    = 0;

    if (blockIdx.x == 0 && threadIdx.x < 32) {
        int lane = threadIdx.x;
        int nz0 = 0, nz1 = 0, nz2 = 0, nz3 = 0, c01 = 0, c3F = 0;
        for (int base = 0; base < 4096; base += 32) {
            unsigned char b = m[base + lane];        // (base+lane)&3 == lane&3
            unsigned nzm = __ballot_sync(0xFFFFFFFFu, b != 0);
            unsigned m01 = __ballot_sync(0xFFFFFFFFu, b == 0x01);
            unsigned m3F = __ballot_sync(0xFFFFFFFFu, b == 0x3F);
            nz0 += __popc(nzm & 0x11111111u);
            nz1 += __popc(nzm & 0x22222222u);
            nz2 += __popc(nzm & 0x44444444u);
            nz3 += __popc(nzm & 0x88888888u);
            c01 += __popc(m01);
            c3F += __popc(m3F);
        }
        if (lane == 0) {
            int mode;
            if (nz1 == 0 && nz2 == 0 && nz3 == 0)
                mode = 1;                                        // int32 (0/1, LE)
            else if (c01 == 0 && c3F > 0)
                mode = (nz0 == 0 && nz1 == 0) ? 2 : 3;           // float32 : bf16
            else
                mode = 0;                                        // uint8 bool
            g_mode = mode;
        }
    }
}

__device__ __forceinline__ bool read_mask(const unsigned char* p, int node, int mode) {
    if (mode == 1) return ((const int*)p)[node] != 0;
    if (mode == 2) return ((const float*)p)[node] != 0.0f;
    if (mode == 3) return ((const unsigned short*)p)[node] != 0;
    return p[node] != 0;
}

// ---------------------------------------------------------------- degree (vectorized)
__global__ void k_deg(const int4* __restrict__ row4, const float4* __restrict__ w4) {
    int e = blockIdx.x * blockDim.x + threadIdx.x;
    if (e < E_EDGES / 4) {
        int4   r = row4[e];
        float4 w = w4[e];
        atomicAdd(&g_deg[r.x], w.x);
        atomicAdd(&g_deg[r.y], w.y);
        atomicAdd(&g_deg[r.z], w.z);
        atomicAdd(&g_deg[r.w], w.w);
    }
}

// ---------------------------------------------------------------- per-node: softmax / mask / dinv / q / self-loop diag
// Register-direct, thread-per-node. Each thread owns its 128B row (full-sector loads).
__global__ __launch_bounds__(256) void k_node(const float* __restrict__ x,
                                              const float* __restrict__ y,
                                              const unsigned char* __restrict__ mask) {
    __shared__ float sdiag[C];
    int tid = threadIdx.x;
    if (tid < C) sdiag[tid] = 0.0f;
    __syncthreads();

    int node = blockIdx.x * 256 + tid;
    if (node < N_NODES) {
        int  mode = g_mode;
        bool msk  = read_mask(mask, node, mode);
        float dinv = rsqrtf(g_deg[node]);        // deg >= 1 always
        unsigned packed[16];
        unsigned enc;

        if (msk) {
            // label = argmax of one-hot row (only masked nodes need y)
            const float4* yr = (const float4*)(y + (size_t)node * C);
            int lab = 0;
            #pragma unroll
            for (int i = 0; i < 8; i++) {
                float4 q = yr[i];
                lab = (q.x > 0.5f) ? 4 * i     : lab;
                lab = (q.y > 0.5f) ? 4 * i + 1 : lab;
                lab = (q.z > 0.5f) ? 4 * i + 2 : lab;
                lab = (q.w > 0.5f) ? 4 * i + 3 : lab;
            }
            __nv_bfloat16 h = __float2bfloat16(dinv);
            unsigned hb;
            { unsigned short s; memcpy(&s, &h, 2); hb = s; }
            #pragma unroll
            for (int i = 0; i < 16; i++) {
                unsigned lo = (lab == 2 * i)     ? hb : 0u;
                unsigned hi = (lab == 2 * i + 1) ? hb : 0u;
                packed[i] = lo | (hi << 16);
            }
            atomicAdd(&sdiag[lab], dinv * dinv);             // self-loop diag
            enc = (__float_as_uint(dinv) & ~63u) | 32u | (unsigned)lab;
        } else {
            const float4* xr = (const float4*)(x + (size_t)node * C);
            float v[32];
            #pragma unroll
            for (int i = 0; i < 8; i++) {
                float4 q = xr[i];
                v[4*i] = q.x; v[4*i+1] = q.y; v[4*i+2] = q.z; v[4*i+3] = q.w;
            }
            float m0 = v[0], m1 = v[1], m2 = v[2], m3 = v[3];
            #pragma unroll
            for (int r = 4; r < 32; r += 4) {
                m0 = fmaxf(m0, v[r]); m1 = fmaxf(m1, v[r+1]);
                m2 = fmaxf(m2, v[r+2]); m3 = fmaxf(m3, v[r+3]);
            }
            float mx = fmaxf(fmaxf(m0, m1), fmaxf(m2, m3));
            float a0 = 0.f, a1 = 0.f, a2 = 0.f, a3 = 0.f;
            #pragma unroll
            for (int r = 0; r < 32; r += 4) {
                v[r]   = __expf(v[r]   - mx); a0 += v[r];
                v[r+1] = __expf(v[r+1] - mx); a1 += v[r+1];
                v[r+2] = __expf(v[r+2] - mx); a2 += v[r+2];
                v[r+3] = __expf(v[r+3] - mx); a3 += v[r+3];
            }
            float f = dinv / ((a0 + a1) + (a2 + a3));
            #pragma unroll
            for (int i = 0; i < 16; i++) {
                __nv_bfloat162 hh = __float22bfloat162_rn(make_float2(v[2*i] * f, v[2*i+1] * f));
                memcpy(&packed[i], &hh, 4);
            }
            enc = __float_as_uint(dinv) & ~63u;
        }

        uint4* dst = (uint4*)(g_qh + (size_t)node * C);
        dst[0] = make_uint4(packed[0],  packed[1],  packed[2],  packed[3]);
        dst[1] = make_uint4(packed[4],  packed[5],  packed[6],  packed[7]);
        dst[2] = make_uint4(packed[8],  packed[9],  packed[10], packed[11]);
        dst[3] = make_uint4(packed[12], packed[13], packed[14], packed[15]);
        g_ld[node] = __uint_as_float(enc);
    }
    __syncthreads();
    if (tid < C && sdiag[tid] != 0.0f) atomicAdd(&g_H[tid * C + tid], sdiag[tid]);
}

// ---------------------------------------------------------------- compaction: 4 edges/thread, warp-scan offsets
__global__ __launch_bounds__(256) void k_compact(const int4* __restrict__ row4,
                                                 const int4* __restrict__ col4,
                                                 const float4* __restrict__ w4) {
    int i = blockIdx.x * blockDim.x + threadIdx.x;
    int lane = threadIdx.x & 31;
    if (i >= E_EDGES / 4) return;

    int4   rr = row4[i];
    int4   cc = col4[i];
    float4 ww = w4[i];

    float d0 = g_ld[rr.x], d1 = g_ld[rr.y], d2 = g_ld[rr.z], d3 = g_ld[rr.w];
    unsigned t0 = __float_as_uint(d0) & 63u;
    unsigned t1 = __float_as_uint(d1) & 63u;
    unsigned t2 = __float_as_uint(d2) & 63u;
    unsigned t3 = __float_as_uint(d3) & 63u;
    bool k0 = t0 >= 32u, k1 = t1 >= 32u, k2 = t2 >= 32u, k3 = t3 >= 32u;

    int cnt = (int)k0 + (int)k1 + (int)k2 + (int)k3;
    // inclusive warp scan
    int ofs = cnt;
    #pragma unroll
    for (int d = 1; d < 32; d <<= 1) {
        int n = __shfl_up_sync(0xFFFFFFFFu, ofs, d);
        if (lane >= d) ofs += n;
    }
    int total = __shfl_sync(0xFFFFFFFFu, ofs, 31);
    int basep = 0;
    if (lane == 31 && total) basep = atomicAdd(&g_cnt, total);
    basep = __shfl_sync(0xFFFFFFFFu, basep, 31);
    int p = basep + ofs - cnt;

    if (k0) g_cmp[p++] = make_int2(cc.x | (int)((t0 - 32u) << 17), __float_as_int(d0 * ww.x));
    if (k1) g_cmp[p++] = make_int2(cc.y | (int)((t1 - 32u) << 17), __float_as_int(d1 * ww.y));
    if (k2) g_cmp[p++] = make_int2(cc.z | (int)((t2 - 32u) << 17), __float_as_int(d2 * ww.z));
    if (k3) g_cmp[p++] = make_int2(cc.w | (int)((t3 - 32u) << 17), __float_as_int(d3 * ww.w));
}

// ---------------------------------------------------------------- dense sweep -> 32x32 tile
// Broadcast model: one edge per inner step; lane j sole owner of column j -> no atomics.
__global__ __launch_bounds__(256) void k_spmm() {
    __shared__ float Hs[SPMM_WARPS][C * C];
    int lane = threadIdx.x & 31;
    int wid  = threadIdx.x >> 5;
    float* Hw = Hs[wid];
    for (int i = lane; i < C * C; i += 32) Hw[i] = 0.0f;
    __syncwarp();

    int total = g_cnt;
    int gw = blockIdx.x * SPMM_WARPS + wid;
    int nw = gridDim.x * SPMM_WARPS;

    for (int base = gw * 32; base < total; base += nw * 32) {
        int e = base + lane;
        int2 ent = (e < total) ? g_cmp[e] : make_int2(0, 0);
        if (base + 32 <= total) {
            #pragma unroll
            for (int k = 0; k < 32; k++) {
                int   pk = __shfl_sync(0xFFFFFFFFu, ent.x, k);
                float v  = __uint_as_float(__shfl_sync(0xFFFFFFFFu, ent.y, k));
                int c = pk & 0x1FFFF;
                int l = pk >> 17;
                float qv = __bfloat162float(g_qh[c * C + lane]);
                Hw[l * C + lane] += v * qv;
            }
        } else {
            int cnt = total - base;
            for (int k = 0; k < cnt; k++) {
                int   pk = __shfl_sync(0xFFFFFFFFu, ent.x, k);
                float v  = __uint_as_float(__shfl_sync(0xFFFFFFFFu, ent.y, k));
                int c = pk & 0x1FFFF;
                int l = pk >> 17;
                float qv = __bfloat162float(g_qh[c * C + lane]);
                Hw[l * C + lane] += v * qv;
            }
        }
    }

    __syncthreads();
    for (int i = threadIdx.x; i < C * C; i += blockDim.x) {
        float s = 0.0f;
        #pragma unroll
        for (int wg = 0; wg < SPMM_WARPS; wg++) s += Hs[wg][i];
        atomicAdd(&g_H[i], s);
    }
}

// ---------------------------------------------------------------- Sinkhorn: tree sums, 2 syncwarps/iter, 1 transpose
__global__ void k_sinkhorn(float* __restrict__ out) {
    __shared__ float ss[C * 33];
    __shared__ float sinv[C];
    int t = threadIdx.x;   // thread t holds column t

    float v[C];
    #pragma unroll
    for (int r = 0; r < C; r++) v[r] = g_H[r * C + t];

    for (int it = 0; it < 3000; it++) {
        // column normalize (local, tree sum)
        float a0 = 0.f, a1 = 0.f, a2 = 0.f, a3 = 0.f;
        #pragma unroll
        for (int r = 0; r < C; r += 4) { a0 += v[r]; a1 += v[r+1]; a2 += v[r+2]; a3 += v[r+3]; }
        float s = (a0 + a1) + (a2 + a3);
        float ic = 1.0f / s;
        #pragma unroll
        for (int r = 0; r < C; r++) { v[r] *= ic; ss[r * 33 + t] = v[r]; }
        __syncwarp();

        // row sum of row t (conflict-free), publish reciprocal
        float b0 = 0.f, b1 = 0.f, b2 = 0.f, b3 = 0.f;
        #pragma unroll
        for (int cc = 0; cc < C; cc += 4) {
            b0 += ss[t * 33 + cc];     b1 += ss[t * 33 + cc + 1];
            b2 += ss[t * 33 + cc + 2]; b3 += ss[t * 33 + cc + 3];
        }
        float s2 = (b0 + b1) + (b2 + b3);
        sinv[t] = 1.0f / s2;
        __syncwarp();

        // row normalize (broadcast reads of sinv)
        #pragma unroll
        for (int r = 0; r < C; r++) v[r] *= sinv[r];

        // both scale factors -> 1 at the fixed point; check every 4 iters
        if ((it & 3) == 3) {
            float dev = fmaxf(fabsf(s - 1.0f), fabsf(s2 - 1.0f));
            if (it >= 7 && __all_sync(0xFFFFFFFFu, dev < 3e-5f)) break;
        }
    }

    #pragma unroll
    for (int r = 0; r < C; r++) out[r * C + t] = v[r];
}

// ---------------------------------------------------------------- launch
extern "C" void kernel_launch(void* const* d_in, const int* in_sizes, int n_in,
                              void* d_out, int out_size) {
    const int*           ei   = (const int*)d_in[0];      // (2, E): rows then cols
    const float*         ew   = (const float*)d_in[1];    // (E,)
    const float*         x    = (const float*)d_in[2];    // (N, C)
    const float*         y    = (const float*)d_in[3];    // (N, C) one-hot
    const unsigned char* mask = (const unsigned char*)d_in[4];  // (N,) dtype sniffed

    const int* row = ei;
    const int* col = ei + E_EDGES;

    k_init<<<(N_NODES + 255) / 256, 256>>>(mask);
    k_deg<<<(E_EDGES / 4 + 255) / 256, 256>>>((const int4*)row, (const float4*)ew);
    k_node<<<(N_NODES + 255) / 256, 256>>>(x, y, mask);
    k_compact<<<(E_EDGES / 4 + 255) / 256, 256>>>((const int4*)row, (const int4*)col, (const float4*)ew);
    k_spmm<<<592, 256>>>();
    k_sinkhorn<<<1, 32>>>((float*)d_out);
}